// round 1
// baseline (speedup 1.0000x reference)
#include <cuda_runtime.h>
#include <cstdint>

// Problem constants (fixed by the dataset)
#define H 256
#define MAXROWS 50000
#define LN_EPS 1e-5f

// Scratch (allocation-free rule: __device__ globals)
__device__ float g_agg[MAXROWS * H];
__device__ float g_t  [MAXROWS * H];
__device__ float g_t2 [MAXROWS * H];

// ---------------------------------------------------------------------------
// zero-fill
// ---------------------------------------------------------------------------
__global__ void zero_kernel(float4* __restrict__ p, int n4) {
    int i = blockIdx.x * blockDim.x + threadIdx.x;
    if (i < n4) p[i] = make_float4(0.f, 0.f, 0.f, 0.f);
}

// ---------------------------------------------------------------------------
// Edge scatter: agg[dst] += relu(x_src[src] + ea*We + be)
// 64 threads per edge (4 floats each), 4 edges per 256-thread block.
// ---------------------------------------------------------------------------
__global__ void edge_scatter_kernel(const float* __restrict__ xsrc,
                                    const int*  __restrict__ src,
                                    const int*  __restrict__ dst,
                                    const float* __restrict__ ea,
                                    const float* __restrict__ We,
                                    const float* __restrict__ be,
                                    float* __restrict__ agg,
                                    int Ecount) {
    int eid = blockIdx.x * 4 + (threadIdx.x >> 6);
    if (eid >= Ecount) return;
    int col = (threadIdx.x & 63) * 4;

    int s = __ldg(src + eid);
    int d = __ldg(dst + eid);
    float a = __ldg(ea + eid);

    float4 x = *(const float4*)(xsrc + (size_t)s * H + col);
    float4 w = __ldg((const float4*)(We + col));
    float4 b = __ldg((const float4*)(be + col));

    float m0 = fmaxf(x.x + fmaf(a, w.x, b.x), 0.f);
    float m1 = fmaxf(x.y + fmaf(a, w.y, b.y), 0.f);
    float m2 = fmaxf(x.z + fmaf(a, w.z, b.z), 0.f);
    float m3 = fmaxf(x.w + fmaf(a, w.w, b.w), 0.f);

    float* o = agg + (size_t)d * H + col;
    atomicAdd(o + 0, m0);
    atomicAdd(o + 1, m1);
    atomicAdd(o + 2, m2);
    atomicAdd(o + 3, m3);
}

// ---------------------------------------------------------------------------
// SGEMM: C[M,256] = f( (A (+A2)) @ B + bias (+res) )
//   ADDA: A_eff = A + A2  (elementwise, used for x_dst + agg)
//   RELU: relu epilogue
//   RES : add residual row (res) in epilogue
// Tiles: BM=128, BN=128, BK=16, 256 threads, 8x8 per thread. K = N = 256.
// ---------------------------------------------------------------------------
#define BM 128
#define BN 128
#define BK 16
#define TM 8
#define TN 8
#define AS_STRIDE 130   // pad so the 4 k-subgroups land 8 banks apart on store

template<bool RELU, bool ADDA, bool RES>
__global__ __launch_bounds__(256) void sgemm256(const float* __restrict__ A,
                                                const float* __restrict__ A2,
                                                const float* __restrict__ B,
                                                const float* __restrict__ bias,
                                                const float* __restrict__ res,
                                                float* __restrict__ C,
                                                int M) {
    __shared__ float As[BK][AS_STRIDE];
    __shared__ float Bs[BK][BN];

    const int bm = blockIdx.x * BM;
    const int bn = blockIdx.y * BN;
    const int t  = threadIdx.x;
    const int tx = t & 15;   // n-dim
    const int ty = t >> 4;   // m-dim

    float acc[TM][TN];
#pragma unroll
    for (int i = 0; i < TM; i++)
#pragma unroll
        for (int j = 0; j < TN; j++) acc[i][j] = 0.f;

    for (int k0 = 0; k0 < H; k0 += BK) {
        // load A tile (BM x BK), transposed into As[k][m]
#pragma unroll
        for (int i = 0; i < 2; i++) {
            int c    = t + i * 256;          // 0..511
            int row  = c >> 2;               // 0..127
            int ksub = (c & 3) * 4;          // 0,4,8,12
            int grow = bm + row;
            float4 v = make_float4(0.f, 0.f, 0.f, 0.f);
            if (grow < M) {
                v = *(const float4*)(A + (size_t)grow * H + k0 + ksub);
                if (ADDA) {
                    float4 u = *(const float4*)(A2 + (size_t)grow * H + k0 + ksub);
                    v.x += u.x; v.y += u.y; v.z += u.z; v.w += u.w;
                }
            }
            As[ksub + 0][row] = v.x;
            As[ksub + 1][row] = v.y;
            As[ksub + 2][row] = v.z;
            As[ksub + 3][row] = v.w;
        }
        // load B tile (BK x BN)
#pragma unroll
        for (int i = 0; i < 2; i++) {
            int c   = t + i * 256;           // 0..511
            int row = c >> 5;                // 0..15
            int col = (c & 31) * 4;          // 0..124
            *(float4*)(&Bs[row][col]) =
                *(const float4*)(B + (size_t)(k0 + row) * H + bn + col);
        }
        __syncthreads();

#pragma unroll
        for (int kk = 0; kk < BK; kk++) {
            float a[TM], b[TN];
#pragma unroll
            for (int i = 0; i < TM; i++) a[i] = As[kk][ty * TM + i];
            const float4* bp = (const float4*)(&Bs[kk][tx * TN]);
            float4 b0 = bp[0], b1 = bp[1];
            b[0] = b0.x; b[1] = b0.y; b[2] = b0.z; b[3] = b0.w;
            b[4] = b1.x; b[5] = b1.y; b[6] = b1.z; b[7] = b1.w;
#pragma unroll
            for (int i = 0; i < TM; i++)
#pragma unroll
                for (int j = 0; j < TN; j++)
                    acc[i][j] = fmaf(a[i], b[j], acc[i][j]);
        }
        __syncthreads();
    }

    // epilogue
#pragma unroll
    for (int i = 0; i < TM; i++) {
        int grow = bm + ty * TM + i;
        if (grow >= M) continue;
#pragma unroll
        for (int j = 0; j < TN; j += 4) {
            int gcol = bn + tx * TN + j;
            float4 bsv = __ldg((const float4*)(bias + gcol));
            float4 v;
            v.x = acc[i][j + 0] + bsv.x;
            v.y = acc[i][j + 1] + bsv.y;
            v.z = acc[i][j + 2] + bsv.z;
            v.w = acc[i][j + 3] + bsv.w;
            if (RES) {
                float4 r = *(const float4*)(res + (size_t)grow * H + gcol);
                v.x += r.x; v.y += r.y; v.z += r.z; v.w += r.w;
            }
            if (RELU) {
                v.x = fmaxf(v.x, 0.f); v.y = fmaxf(v.y, 0.f);
                v.z = fmaxf(v.z, 0.f); v.w = fmaxf(v.w, 0.f);
            }
            *(float4*)(C + (size_t)grow * H + gcol) = v;
        }
    }
}

// ---------------------------------------------------------------------------
// LayerNorm: out = (z - mu) * rsqrt(var + eps) * g + beta
// One warp per row (256 cols = 8 floats/lane), 8 rows per block.
// ---------------------------------------------------------------------------
__global__ void ln_kernel(const float* __restrict__ z,
                          const float* __restrict__ g,
                          const float* __restrict__ beta,
                          float* __restrict__ out, int M) {
    int row = blockIdx.x * 8 + (threadIdx.x >> 5);
    if (row >= M) return;
    int lane = threadIdx.x & 31;
    const float* zr = z + (size_t)row * H + lane * 8;

    float4 v0 = *(const float4*)(zr);
    float4 v1 = *(const float4*)(zr + 4);

    float s = v0.x + v0.y + v0.z + v0.w + v1.x + v1.y + v1.z + v1.w;
#pragma unroll
    for (int o = 16; o > 0; o >>= 1) s += __shfl_xor_sync(0xFFFFFFFFu, s, o);
    float mu = s * (1.f / 256.f);

    float d0 = v0.x - mu, d1 = v0.y - mu, d2 = v0.z - mu, d3 = v0.w - mu;
    float d4 = v1.x - mu, d5 = v1.y - mu, d6 = v1.z - mu, d7 = v1.w - mu;
    float ss = d0*d0 + d1*d1 + d2*d2 + d3*d3 + d4*d4 + d5*d5 + d6*d6 + d7*d7;
#pragma unroll
    for (int o = 16; o > 0; o >>= 1) ss += __shfl_xor_sync(0xFFFFFFFFu, ss, o);
    float rs = rsqrtf(ss * (1.f / 256.f) + LN_EPS);

    float4 gv0 = __ldg((const float4*)(g    + lane * 8));
    float4 gv1 = __ldg((const float4*)(g    + lane * 8 + 4));
    float4 bv0 = __ldg((const float4*)(beta + lane * 8));
    float4 bv1 = __ldg((const float4*)(beta + lane * 8 + 4));

    float4 o0, o1;
    o0.x = d0 * rs * gv0.x + bv0.x;
    o0.y = d1 * rs * gv0.y + bv0.y;
    o0.z = d2 * rs * gv0.z + bv0.z;
    o0.w = d3 * rs * gv0.w + bv0.w;
    o1.x = d4 * rs * gv1.x + bv1.x;
    o1.y = d5 * rs * gv1.y + bv1.y;
    o1.z = d6 * rs * gv1.z + bv1.z;
    o1.w = d7 * rs * gv1.w + bv1.w;

    float* orow = out + (size_t)row * H + lane * 8;
    *(float4*)(orow)     = o0;
    *(float4*)(orow + 4) = o1;
}

// ---------------------------------------------------------------------------
// launch
// ---------------------------------------------------------------------------
extern "C" void kernel_launch(void* const* d_in, const int* in_sizes, int n_in,
                              void* d_out, int out_size) {
    const float* x_var    = (const float*)d_in[0];
    const float* x_constr = (const float*)d_in[1];
    const int*   ei_v2c   = (const int*)  d_in[2];
    const int*   ei_c2v   = (const int*)  d_in[3];
    const float* ea       = (const float*)d_in[4];
    const float* We1 = (const float*)d_in[5];
    const float* be1 = (const float*)d_in[6];
    const float* W1a = (const float*)d_in[7];
    const float* b1a = (const float*)d_in[8];
    const float* W1b = (const float*)d_in[9];
    const float* b1b = (const float*)d_in[10];
    const float* We2 = (const float*)d_in[11];
    const float* be2 = (const float*)d_in[12];
    const float* W2a = (const float*)d_in[13];
    const float* b2a = (const float*)d_in[14];
    const float* W2b = (const float*)d_in[15];
    const float* b2b = (const float*)d_in[16];
    const float* g_constr    = (const float*)d_in[17];
    const float* beta_constr = (const float*)d_in[18];
    const float* g_var       = (const float*)d_in[19];
    const float* beta_var    = (const float*)d_in[20];

    const int NVr = in_sizes[0] / H;
    const int NCr = in_sizes[1] / H;
    const int Ecnt = in_sizes[4];

    float *agg, *t, *t2;
    cudaGetSymbolAddress((void**)&agg, g_agg);
    cudaGetSymbolAddress((void**)&t,   g_t);
    cudaGetSymbolAddress((void**)&t2,  g_t2);

    float* out_var    = (float*)d_out;
    float* out_constr = (float*)d_out + (size_t)NVr * H;

    const int edge_blocks = (Ecnt + 3) / 4;

    // ---- stage 1: var -> constr ----
    {
        int n4 = NCr * H / 4;
        zero_kernel<<<(n4 + 255) / 256, 256>>>((float4*)agg, n4);
        edge_scatter_kernel<<<edge_blocks, 256>>>(x_var, ei_v2c, ei_v2c + Ecnt,
                                                  ea, We1, be1, agg, Ecnt);
        dim3 g1((NCr + BM - 1) / BM, H / BN);
        sgemm256<true,  true,  false><<<g1, 256>>>(x_constr, agg, W1a, b1a, nullptr, t,  NCr);
        sgemm256<false, false, true ><<<g1, 256>>>(t, nullptr, W1b, b1b, x_constr, t2, NCr);
        ln_kernel<<<(NCr + 7) / 8, 256>>>(t2, g_constr, beta_constr, out_constr, NCr);
    }

    // ---- stage 2: constr -> var (uses LN'd x_constr from d_out) ----
    {
        int n4 = NVr * H / 4;
        zero_kernel<<<(n4 + 255) / 256, 256>>>((float4*)agg, n4);
        edge_scatter_kernel<<<edge_blocks, 256>>>(out_constr, ei_c2v, ei_c2v + Ecnt,
                                                  ea, We2, be2, agg, Ecnt);
        dim3 g2((NVr + BM - 1) / BM, H / BN);
        sgemm256<true,  true,  false><<<g2, 256>>>(x_var, agg, W2a, b2a, nullptr, t,  NVr);
        sgemm256<false, false, true ><<<g2, 256>>>(t, nullptr, W2b, b2b, x_var, t2, NVr);
        ln_kernel<<<(NVr + 7) / 8, 256>>>(t2, g_var, beta_var, out_var, NVr);
    }
}

// round 3
// speedup vs baseline: 1.1440x; 1.1440x over previous
#include <cuda_runtime.h>
#include <cuda_bf16.h>
#include <cstdint>

#define H 256
#define MAXROWS 50000
#define LN_EPS 1e-5f

// ---------------------------------------------------------------------------
// Scratch (__device__ globals: allocation-free rule)
// ---------------------------------------------------------------------------
__device__ float g_agg[MAXROWS * H];
__device__ float g_t  [MAXROWS * H];
// Transposed weights as bf16 hi/lo: [which 0..3][hi/lo][n*H + k]
__device__ __nv_bfloat16 g_wt[4][2][H * H];

// ---------------------------------------------------------------------------
// PTX helpers (base compute_103: mma.sync / ldmatrix / cp.async only)
// ---------------------------------------------------------------------------
__device__ __forceinline__ uint32_t smem_u32(const void* p) {
    uint32_t a;
    asm("{ .reg .u64 t; cvta.to.shared.u64 t, %1; cvt.u32.u64 %0, t; }"
        : "=r"(a) : "l"(p));
    return a;
}
__device__ __forceinline__ void ldsm_x4(uint32_t r[4], uint32_t addr) {
    asm volatile("ldmatrix.sync.aligned.m8n8.x4.shared.b16 {%0,%1,%2,%3}, [%4];"
                 : "=r"(r[0]), "=r"(r[1]), "=r"(r[2]), "=r"(r[3]) : "r"(addr));
}
__device__ __forceinline__ void mma_bf16(float c[4],
                                         const uint32_t a[4],
                                         uint32_t b0, uint32_t b1) {
    asm volatile(
        "mma.sync.aligned.m16n8k16.row.col.f32.bf16.bf16.f32 "
        "{%0,%1,%2,%3}, {%4,%5,%6,%7}, {%8,%9}, {%0,%1,%2,%3};"
        : "+f"(c[0]), "+f"(c[1]), "+f"(c[2]), "+f"(c[3])
        : "r"(a[0]), "r"(a[1]), "r"(a[2]), "r"(a[3]), "r"(b0), "r"(b1));
}
__device__ __forceinline__ void cp16(uint32_t dst, const void* src) {
    asm volatile("cp.async.ca.shared.global [%0], [%1], 16;"
                 :: "r"(dst), "l"(src) : "memory");
}
#define CP_COMMIT() asm volatile("cp.async.commit_group;" ::: "memory")
#define CP_WAIT1()  asm volatile("cp.async.wait_group 1;" ::: "memory")
#define CP_WAIT0()  asm volatile("cp.async.wait_group 0;" ::: "memory")

__device__ __forceinline__ uint32_t pack2(float a, float b) {
    __nv_bfloat162 h = __floats2bfloat162_rn(a, b);
    return *(uint32_t*)&h;
}

// ---------------------------------------------------------------------------
// SMEM layout (bytes). A tiles: [64][40] bf16 (stride 80B). B: [256][40] bf16.
// ---------------------------------------------------------------------------
#define SM_AH(st)  ((st) * 5120)            // 2 x 5120
#define SM_AL(st)  (10240 + (st) * 5120)    // AL = AH + 10240
#define SM_BH(st)  (20480 + (st) * 20480)   // 2 x 20480
#define SM_BL(st)  (61440 + (st) * 20480)   // BL = BH + 40960
#define SM_BIAS    102400
#define SM_G       103424
#define SM_BETA    104448
#define SM_PSUM    105472
#define SM_PSQ     105728
#define SMEM_T     106496

// ---------------------------------------------------------------------------
// zero-fill
// ---------------------------------------------------------------------------
__global__ void zero_kernel(float4* __restrict__ p, int n4) {
    int i = blockIdx.x * blockDim.x + threadIdx.x;
    if (i < n4) p[i] = make_float4(0.f, 0.f, 0.f, 0.f);
}

// ---------------------------------------------------------------------------
// Weight prep: Wt_hi/lo[n][k] = split_bf16( W[k][n] )
// ---------------------------------------------------------------------------
__global__ void wprep_kernel(const float* __restrict__ W,
                             __nv_bfloat16* __restrict__ hi,
                             __nv_bfloat16* __restrict__ lo) {
    int i = blockIdx.x * 256 + threadIdx.x;
    int n = i >> 8, k = i & 255;
    float v = W[k * H + n];
    __nv_bfloat16 h = __float2bfloat16(v);
    hi[i] = h;
    lo[i] = __float2bfloat16(v - __bfloat162float(h));
}

// ---------------------------------------------------------------------------
// Edge scatter: agg[dst] += relu(x_src[src] + ea*We + be)
// ---------------------------------------------------------------------------
__global__ void edge_scatter_kernel(const float* __restrict__ xsrc,
                                    const int*  __restrict__ src,
                                    const int*  __restrict__ dst,
                                    const float* __restrict__ ea,
                                    const float* __restrict__ We,
                                    const float* __restrict__ be,
                                    float* __restrict__ agg,
                                    int Ecount) {
    int eid = blockIdx.x * 4 + (threadIdx.x >> 6);
    if (eid >= Ecount) return;
    int col = (threadIdx.x & 63) * 4;

    int s = __ldg(src + eid);
    int d = __ldg(dst + eid);
    float a = __ldg(ea + eid);

    float4 x = *(const float4*)(xsrc + (size_t)s * H + col);
    float4 w = __ldg((const float4*)(We + col));
    float4 b = __ldg((const float4*)(be + col));

    float m0 = fmaxf(x.x + fmaf(a, w.x, b.x), 0.f);
    float m1 = fmaxf(x.y + fmaf(a, w.y, b.y), 0.f);
    float m2 = fmaxf(x.z + fmaf(a, w.z, b.z), 0.f);
    float m3 = fmaxf(x.w + fmaf(a, w.w, b.w), 0.f);

    float* o = agg + (size_t)d * H + col;
    atomicAdd(o + 0, m0);
    atomicAdd(o + 1, m1);
    atomicAdd(o + 2, m2);
    atomicAdd(o + 3, m3);
}

// ---------------------------------------------------------------------------
// HMMA GEMM: C[M,256] = epilogue( (A0 (+A1)) @ Wt^T + bias )
//   LN_EPI=0: relu(acc+bias)
//   LN_EPI=1: LayerNorm(acc+bias+res)*g+beta
// Tile: 64M x 256N, BK=32, double-buffered. 8 warps (2m x 4n), warp 32x64.
// 3 bf16 passes: Ah*Bh + Ah*Bl + Al*Bh.
// ---------------------------------------------------------------------------
template<bool LN_EPI, bool ADDA>
__global__ __launch_bounds__(256) void tc_gemm(
    const float* __restrict__ A0, const float* __restrict__ A1,
    const __nv_bfloat16* __restrict__ WtHi, const __nv_bfloat16* __restrict__ WtLo,
    const float* __restrict__ bias,
    const float* __restrict__ res,
    const float* __restrict__ gln, const float* __restrict__ bln,
    float* __restrict__ C, int M)
{
    extern __shared__ char sm[];
    const uint32_t sb = smem_u32(sm);

    const int t = threadIdx.x;
    const int lane = t & 31;
    const int wid = t >> 5;
    const int wm = wid & 1;       // 2 m-warps
    const int wn = wid >> 1;      // 4 n-warps
    const int bm = blockIdx.x * 64;

    float* biasS = (float*)(sm + SM_BIAS);
    float* gS    = (float*)(sm + SM_G);
    float* bS    = (float*)(sm + SM_BETA);
    float* psum  = (float*)(sm + SM_PSUM);
    float* psq   = (float*)(sm + SM_PSQ);

    biasS[t] = bias[t];
    if (LN_EPI) {
        gS[t] = gln[t];
        bS[t] = bln[t];
        if (t < 64) { psum[t] = 0.f; psq[t] = 0.f; }
    }

    float c[2][8][4];
#pragma unroll
    for (int i = 0; i < 2; i++)
#pragma unroll
        for (int j = 0; j < 8; j++)
#pragma unroll
            for (int e = 0; e < 4; e++) c[i][j][e] = 0.f;

    // A loader coords: each thread loads 8 floats of a 64x32 chunk
    const int row_a = t >> 2;        // 0..63
    const int kq_a  = t & 3;         // 0..3 (8 floats each)
    const int grow_a = bm + row_a;
    const bool aval = (grow_a < M);

    // --- A global->reg ---
    auto lda = [&](int ck, float4& v0, float4& v1) {
        if (aval) {
            size_t off = (size_t)grow_a * H + ck * 32 + kq_a * 8;
            const float4* p = (const float4*)(A0 + off);
            v0 = p[0]; v1 = p[1];
            if (ADDA) {
                const float4* q = (const float4*)(A1 + off);
                float4 u0 = q[0], u1 = q[1];
                v0.x += u0.x; v0.y += u0.y; v0.z += u0.z; v0.w += u0.w;
                v1.x += u1.x; v1.y += u1.y; v1.z += u1.z; v1.w += u1.w;
            }
        } else {
            v0 = make_float4(0.f, 0.f, 0.f, 0.f);
            v1 = v0;
        }
    };
    // --- A reg->smem (split hi/lo) ---
    auto sts_a = [&](int st, float4 v0, float4 v1) {
        float x[8] = {v0.x, v0.y, v0.z, v0.w, v1.x, v1.y, v1.z, v1.w};
        uint32_t hv[4], lv[4];
#pragma unroll
        for (int j = 0; j < 4; j++) {
            __nv_bfloat16 h0 = __float2bfloat16(x[2*j]);
            __nv_bfloat16 h1 = __float2bfloat16(x[2*j+1]);
            float l0 = x[2*j]   - __bfloat162float(h0);
            float l1 = x[2*j+1] - __bfloat162float(h1);
            hv[j] = pack2(__bfloat162float(h0), __bfloat162float(h1));
            lv[j] = pack2(l0, l1);
        }
        uint32_t o = (uint32_t)(row_a * 80 + kq_a * 16);
        *(uint4*)(sm + SM_AH(st) + o) = make_uint4(hv[0], hv[1], hv[2], hv[3]);
        *(uint4*)(sm + SM_AL(st) + o) = make_uint4(lv[0], lv[1], lv[2], lv[3]);
    };
    // --- B global->smem via cp.async (row n = t, 4x16B hi + 4x16B lo) ---
    auto cpb = [&](int ck, int st) {
        const __nv_bfloat16* sh = WtHi + (size_t)t * H + ck * 32;
        const __nv_bfloat16* sl = WtLo + (size_t)t * H + ck * 32;
        uint32_t dh = sb + SM_BH(st) + t * 80;
        uint32_t dl = sb + SM_BL(st) + t * 80;
#pragma unroll
        for (int q = 0; q < 4; q++) {
            cp16(dh + q * 16, sh + q * 8);
            cp16(dl + q * 16, sl + q * 8);
        }
    };

    // ldmatrix lane coordinates
    const uint32_t a_off = (uint32_t)((lane & 15) * 80 + (lane >> 4) * 16);
    const uint32_t b_row = (uint32_t)(wn * 64 + (lane & 7) + ((lane >> 4) * 8));
    const uint32_t b_koff = (uint32_t)(((lane >> 3) & 1) * 16);

    // pipeline
    float4 p0, p1, n0, n1;
    lda(0, p0, p1);
    cpb(0, 0);
    CP_COMMIT();

#pragma unroll 1
    for (int ck = 0; ck < 8; ck++) {
        const int st = ck & 1;
        sts_a(st, p0, p1);
        if (ck < 7) {
            lda(ck + 1, n0, n1);
            cpb(ck + 1, st ^ 1);
            CP_COMMIT();
            CP_WAIT1();
        } else {
            CP_WAIT0();
        }
        __syncthreads();

        // compute chunk (2 k16-steps)
        const uint32_t ah_base = sb + SM_AH(st) + (uint32_t)(wm * 32 * 80) + a_off;
        const uint32_t bh_base = sb + SM_BH(st) + b_row * 80 + b_koff;
#pragma unroll
        for (int ks = 0; ks < 2; ks++) {
            uint32_t ah0[4], ah1[4], al0[4], al1[4];
            uint32_t ab = ah_base + ks * 32;
            ldsm_x4(ah0, ab);
            ldsm_x4(ah1, ab + 16 * 80);
            ldsm_x4(al0, ab + 10240);
            ldsm_x4(al1, ab + 10240 + 16 * 80);
#pragma unroll
            for (int nf4 = 0; nf4 < 4; nf4++) {
                uint32_t bh[4], bl[4];
                uint32_t bb = bh_base + (uint32_t)(nf4 * 16 * 80) + ks * 32;
                ldsm_x4(bh, bb);
                ldsm_x4(bl, bb + 40960);
                const int nf = nf4 * 2;
                // (Ah,Bh)
                mma_bf16(c[0][nf],     ah0, bh[0], bh[1]);
                mma_bf16(c[0][nf + 1], ah0, bh[2], bh[3]);
                mma_bf16(c[1][nf],     ah1, bh[0], bh[1]);
                mma_bf16(c[1][nf + 1], ah1, bh[2], bh[3]);
                // (Ah,Bl)
                mma_bf16(c[0][nf],     ah0, bl[0], bl[1]);
                mma_bf16(c[0][nf + 1], ah0, bl[2], bl[3]);
                mma_bf16(c[1][nf],     ah1, bl[0], bl[1]);
                mma_bf16(c[1][nf + 1], ah1, bl[2], bl[3]);
                // (Al,Bh)
                mma_bf16(c[0][nf],     al0, bh[0], bh[1]);
                mma_bf16(c[0][nf + 1], al0, bh[2], bh[3]);
                mma_bf16(c[1][nf],     al1, bh[0], bh[1]);
                mma_bf16(c[1][nf + 1], al1, bh[2], bh[3]);
            }
        }
        __syncthreads();
        p0 = n0; p1 = n1;
    }

    // ---- epilogue ----
    const int qrow = lane >> 2;
    const int qcol = lane & 3;

    if (!LN_EPI) {
#pragma unroll
        for (int mf = 0; mf < 2; mf++)
#pragma unroll
            for (int rh = 0; rh < 2; rh++) {
                int r = wm * 32 + mf * 16 + rh * 8 + qrow;
                int grow = bm + r;
                if (grow >= M) continue;
                float* crow = C + (size_t)grow * H;
#pragma unroll
                for (int nf = 0; nf < 8; nf++) {
                    int col = wn * 64 + nf * 8 + qcol * 2;
                    float2 v;
                    v.x = fmaxf(c[mf][nf][rh * 2]     + biasS[col],     0.f);
                    v.y = fmaxf(c[mf][nf][rh * 2 + 1] + biasS[col + 1], 0.f);
                    *(float2*)(crow + col) = v;
                }
            }
    } else {
        // z = acc + bias + res; stats
#pragma unroll
        for (int mf = 0; mf < 2; mf++)
#pragma unroll
            for (int rh = 0; rh < 2; rh++) {
                int r = wm * 32 + mf * 16 + rh * 8 + qrow;
                int grow = bm + r;
                float su = 0.f, sq = 0.f;
                if (grow < M) {
                    const float* rrow = res + (size_t)grow * H;
#pragma unroll
                    for (int nf = 0; nf < 8; nf++) {
                        int col = wn * 64 + nf * 8 + qcol * 2;
                        float2 rv = *(const float2*)(rrow + col);
                        float z0 = c[mf][nf][rh * 2]     + biasS[col]     + rv.x;
                        float z1 = c[mf][nf][rh * 2 + 1] + biasS[col + 1] + rv.y;
                        c[mf][nf][rh * 2]     = z0;
                        c[mf][nf][rh * 2 + 1] = z1;
                        su += z0 + z1;
                        sq += z0 * z0 + z1 * z1;
                    }
                }
                su += __shfl_xor_sync(0xFFFFFFFFu, su, 1);
                su += __shfl_xor_sync(0xFFFFFFFFu, su, 2);
                sq += __shfl_xor_sync(0xFFFFFFFFu, sq, 1);
                sq += __shfl_xor_sync(0xFFFFFFFFu, sq, 2);
                if (qcol == 0 && grow < M) {
                    atomicAdd(&psum[r], su);
                    atomicAdd(&psq[r], sq);
                }
            }
        __syncthreads();
#pragma unroll
        for (int mf = 0; mf < 2; mf++)
#pragma unroll
            for (int rh = 0; rh < 2; rh++) {
                int r = wm * 32 + mf * 16 + rh * 8 + qrow;
                int grow = bm + r;
                if (grow >= M) continue;
                float mu = psum[r] * (1.f / 256.f);
                float var = psq[r] * (1.f / 256.f) - mu * mu;
                float rs = rsqrtf(var + LN_EPS);
                float* crow = C + (size_t)grow * H;
#pragma unroll
                for (int nf = 0; nf < 8; nf++) {
                    int col = wn * 64 + nf * 8 + qcol * 2;
                    float2 o;
                    o.x = (c[mf][nf][rh * 2]     - mu) * rs * gS[col]     + bS[col];
                    o.y = (c[mf][nf][rh * 2 + 1] - mu) * rs * gS[col + 1] + bS[col + 1];
                    *(float2*)(crow + col) = o;
                }
            }
    }
}

// ---------------------------------------------------------------------------
// launch
// ---------------------------------------------------------------------------
extern "C" void kernel_launch(void* const* d_in, const int* in_sizes, int n_in,
                              void* d_out, int out_size) {
    const float* x_var    = (const float*)d_in[0];
    const float* x_constr = (const float*)d_in[1];
    const int*   ei_v2c   = (const int*)  d_in[2];
    const int*   ei_c2v   = (const int*)  d_in[3];
    const float* ea       = (const float*)d_in[4];
    const float* We1 = (const float*)d_in[5];
    const float* be1 = (const float*)d_in[6];
    const float* W1a = (const float*)d_in[7];
    const float* b1a = (const float*)d_in[8];
    const float* W1b = (const float*)d_in[9];
    const float* b1b = (const float*)d_in[10];
    const float* We2 = (const float*)d_in[11];
    const float* be2 = (const float*)d_in[12];
    const float* W2a = (const float*)d_in[13];
    const float* b2a = (const float*)d_in[14];
    const float* W2b = (const float*)d_in[15];
    const float* b2b = (const float*)d_in[16];
    const float* g_constr    = (const float*)d_in[17];
    const float* beta_constr = (const float*)d_in[18];
    const float* g_var       = (const float*)d_in[19];
    const float* beta_var    = (const float*)d_in[20];

    const int NVr = in_sizes[0] / H;
    const int NCr = in_sizes[1] / H;
    const int Ecnt = in_sizes[4];

    float *agg, *t;
    cudaGetSymbolAddress((void**)&agg, g_agg);
    cudaGetSymbolAddress((void**)&t,   g_t);
    __nv_bfloat16* wt;
    cudaGetSymbolAddress((void**)&wt, g_wt);
    __nv_bfloat16* wt1a_h = wt;             __nv_bfloat16* wt1a_l = wt + H*H;
    __nv_bfloat16* wt1b_h = wt + 2*H*H;     __nv_bfloat16* wt1b_l = wt + 3*H*H;
    __nv_bfloat16* wt2a_h = wt + 4*H*H;     __nv_bfloat16* wt2a_l = wt + 5*H*H;
    __nv_bfloat16* wt2b_h = wt + 6*H*H;     __nv_bfloat16* wt2b_l = wt + 7*H*H;

    cudaFuncSetAttribute(tc_gemm<false, true>,
                         cudaFuncAttributeMaxDynamicSharedMemorySize, SMEM_T);
    cudaFuncSetAttribute(tc_gemm<true, false>,
                         cudaFuncAttributeMaxDynamicSharedMemorySize, SMEM_T);

    float* out_var    = (float*)d_out;
    float* out_constr = (float*)d_out + (size_t)NVr * H;

    const int edge_blocks = (Ecnt + 3) / 4;

    // weight prep
    wprep_kernel<<<H*H/256, 256>>>(W1a, wt1a_h, wt1a_l);
    wprep_kernel<<<H*H/256, 256>>>(W1b, wt1b_h, wt1b_l);
    wprep_kernel<<<H*H/256, 256>>>(W2a, wt2a_h, wt2a_l);
    wprep_kernel<<<H*H/256, 256>>>(W2b, wt2b_h, wt2b_l);

    // ---- stage 1: var -> constr ----
    {
        int n4 = NCr * H / 4;
        zero_kernel<<<(n4 + 255) / 256, 256>>>((float4*)agg, n4);
        edge_scatter_kernel<<<edge_blocks, 256>>>(x_var, ei_v2c, ei_v2c + Ecnt,
                                                  ea, We1, be1, agg, Ecnt);
        int gx = (NCr + 63) / 64;
        tc_gemm<false, true><<<gx, 256, SMEM_T>>>(
            x_constr, agg, wt1a_h, wt1a_l, b1a, nullptr, nullptr, nullptr, t, NCr);
        tc_gemm<true, false><<<gx, 256, SMEM_T>>>(
            t, nullptr, wt1b_h, wt1b_l, b1b, x_constr, g_constr, beta_constr,
            out_constr, NCr);
    }

    // ---- stage 2: constr -> var (reads LN'd x_constr from d_out) ----
    {
        int n4 = NVr * H / 4;
        zero_kernel<<<(n4 + 255) / 256, 256>>>((float4*)agg, n4);
        edge_scatter_kernel<<<edge_blocks, 256>>>(out_constr, ei_c2v, ei_c2v + Ecnt,
                                                  ea, We2, be2, agg, Ecnt);
        int gx = (NVr + 63) / 64;
        tc_gemm<false, true><<<gx, 256, SMEM_T>>>(
            x_var, agg, wt2a_h, wt2a_l, b2a, nullptr, nullptr, nullptr, t, NVr);
        tc_gemm<true, false><<<gx, 256, SMEM_T>>>(
            t, nullptr, wt2b_h, wt2b_l, b2b, x_var, g_var, beta_var,
            out_var, NVr);
    }
}

// round 4
// speedup vs baseline: 1.5081x; 1.3183x over previous
#include <cuda_runtime.h>
#include <cuda_bf16.h>
#include <cstdint>

#define H 256
#define MAXROWS 50000
#define LN_EPS 1e-5f

// ---------------------------------------------------------------------------
// Scratch (__device__ globals: allocation-free rule)
// ---------------------------------------------------------------------------
__device__ float g_agg[MAXROWS * H];
__device__ float g_t  [MAXROWS * H];
// Transposed weights as bf16 hi/lo: [which 0..3][hi/lo][n*H + k]
__device__ __nv_bfloat16 g_wt[4][2][H * H];

// ---------------------------------------------------------------------------
// PTX helpers (base compute_103: mma.sync / ldmatrix / cp.async / red.v4)
// ---------------------------------------------------------------------------
__device__ __forceinline__ uint32_t smem_u32(const void* p) {
    uint32_t a;
    asm("{ .reg .u64 t; cvta.to.shared.u64 t, %1; cvt.u32.u64 %0, t; }"
        : "=r"(a) : "l"(p));
    return a;
}
__device__ __forceinline__ void ldsm_x4(uint32_t r[4], uint32_t addr) {
    asm volatile("ldmatrix.sync.aligned.m8n8.x4.shared.b16 {%0,%1,%2,%3}, [%4];"
                 : "=r"(r[0]), "=r"(r[1]), "=r"(r[2]), "=r"(r[3]) : "r"(addr));
}
__device__ __forceinline__ void mma_bf16(float c[4],
                                         const uint32_t a[4],
                                         uint32_t b0, uint32_t b1) {
    asm volatile(
        "mma.sync.aligned.m16n8k16.row.col.f32.bf16.bf16.f32 "
        "{%0,%1,%2,%3}, {%4,%5,%6,%7}, {%8,%9}, {%0,%1,%2,%3};"
        : "+f"(c[0]), "+f"(c[1]), "+f"(c[2]), "+f"(c[3])
        : "r"(a[0]), "r"(a[1]), "r"(a[2]), "r"(a[3]), "r"(b0), "r"(b1));
}
__device__ __forceinline__ void cp16(uint32_t dst, const void* src) {
    asm volatile("cp.async.ca.shared.global [%0], [%1], 16;"
                 :: "r"(dst), "l"(src) : "memory");
}
#define CP_COMMIT() asm volatile("cp.async.commit_group;" ::: "memory")
#define CP_WAIT1()  asm volatile("cp.async.wait_group 1;" ::: "memory")
#define CP_WAIT0()  asm volatile("cp.async.wait_group 0;" ::: "memory")

__device__ __forceinline__ void red_v4(float* addr, float a, float b,
                                       float c, float d) {
    asm volatile("red.global.add.v4.f32 [%0], {%1,%2,%3,%4};"
                 :: "l"(addr), "f"(a), "f"(b), "f"(c), "f"(d) : "memory");
}

__device__ __forceinline__ uint32_t pack2(float a, float b) {
    __nv_bfloat162 h = __floats2bfloat162_rn(a, b);
    return *(uint32_t*)&h;
}

// ---------------------------------------------------------------------------
// SMEM layout (bytes). A tiles: [64][40] bf16 (stride 80B). B: [256][40] bf16.
// ---------------------------------------------------------------------------
#define SM_AH(st)  ((st) * 5120)            // 2 x 5120
#define SM_AL(st)  (10240 + (st) * 5120)    // AL = AH + 10240
#define SM_BH(st)  (20480 + (st) * 20480)   // 2 x 20480
#define SM_BL(st)  (61440 + (st) * 20480)   // BL = BH + 40960
#define SM_BIAS    102400
#define SM_G       103424
#define SM_BETA    104448
#define SM_PSUM    105472
#define SM_PSQ     105728
#define SMEM_T     106496

// ---------------------------------------------------------------------------
// zero-fill
// ---------------------------------------------------------------------------
__global__ void zero_kernel(float4* __restrict__ p, int n4) {
    int i = blockIdx.x * blockDim.x + threadIdx.x;
    if (i < n4) p[i] = make_float4(0.f, 0.f, 0.f, 0.f);
}

// ---------------------------------------------------------------------------
// Weight prep (coalesced, smem transpose): Wt_hi/lo[n][k] = split(W[k][n])
// 256 threads (32x8), 32x32 tiles, 64 blocks per weight.
// ---------------------------------------------------------------------------
__global__ void wprep_kernel(const float* __restrict__ W,
                             __nv_bfloat16* __restrict__ hi,
                             __nv_bfloat16* __restrict__ lo) {
    __shared__ float tile[32][33];
    const int tx = threadIdx.x & 31;
    const int ty = threadIdx.x >> 5;          // 0..7
    const int bx = blockIdx.x & 7;            // n-tile
    const int by = blockIdx.x >> 3;           // k-tile
#pragma unroll
    for (int i = 0; i < 4; i++)
        tile[ty + i * 8][tx] = W[(by * 32 + ty + i * 8) * H + bx * 32 + tx];
    __syncthreads();
#pragma unroll
    for (int i = 0; i < 4; i++) {
        float v = tile[tx][ty + i * 8];
        __nv_bfloat16 h = __float2bfloat16(v);
        int n = bx * 32 + ty + i * 8;
        int k = by * 32 + tx;
        hi[n * H + k] = h;
        lo[n * H + k] = __float2bfloat16(v - __bfloat162float(h));
    }
}

// ---------------------------------------------------------------------------
// Edge scatter: agg[dst] += relu(x_src[src] + ea*We + be)   (vector RED)
// ---------------------------------------------------------------------------
__global__ void edge_scatter_kernel(const float* __restrict__ xsrc,
                                    const int*  __restrict__ src,
                                    const int*  __restrict__ dst,
                                    const float* __restrict__ ea,
                                    const float* __restrict__ We,
                                    const float* __restrict__ be,
                                    float* __restrict__ agg,
                                    int Ecount) {
    int eid = blockIdx.x * 4 + (threadIdx.x >> 6);
    if (eid >= Ecount) return;
    int col = (threadIdx.x & 63) * 4;

    int s = __ldg(src + eid);
    int d = __ldg(dst + eid);
    float a = __ldg(ea + eid);

    float4 x = *(const float4*)(xsrc + (size_t)s * H + col);
    float4 w = __ldg((const float4*)(We + col));
    float4 b = __ldg((const float4*)(be + col));

    float m0 = fmaxf(x.x + fmaf(a, w.x, b.x), 0.f);
    float m1 = fmaxf(x.y + fmaf(a, w.y, b.y), 0.f);
    float m2 = fmaxf(x.z + fmaf(a, w.z, b.z), 0.f);
    float m3 = fmaxf(x.w + fmaf(a, w.w, b.w), 0.f);

    red_v4(agg + (size_t)d * H + col, m0, m1, m2, m3);
}

// ---------------------------------------------------------------------------
// HMMA GEMM: C[M,256] = epilogue( (A0 (+A1)) @ Wt^T + bias )
//   LN_EPI=0: relu(acc+bias)
//   LN_EPI=1: LayerNorm(acc+bias+res)*g+beta
// Tile: 64M x 256N, BK=32, double-buffered. 8 warps (2m x 4n), warp 32x64.
// 3 bf16 passes issued PASS-MAJOR (reuse distance 16) to avoid RAW stalls.
// ---------------------------------------------------------------------------
template<bool LN_EPI, bool ADDA>
__global__ __launch_bounds__(256) void tc_gemm(
    const float* __restrict__ A0, const float* __restrict__ A1,
    const __nv_bfloat16* __restrict__ WtHi, const __nv_bfloat16* __restrict__ WtLo,
    const float* __restrict__ bias,
    const float* __restrict__ res,
    const float* __restrict__ gln, const float* __restrict__ bln,
    float* __restrict__ C, int M)
{
    extern __shared__ char sm[];
    const uint32_t sb = smem_u32(sm);

    const int t = threadIdx.x;
    const int lane = t & 31;
    const int wid = t >> 5;
    const int wm = wid & 1;       // 2 m-warps
    const int wn = wid >> 1;      // 4 n-warps
    const int bm = blockIdx.x * 64;

    float* biasS = (float*)(sm + SM_BIAS);
    float* gS    = (float*)(sm + SM_G);
    float* bS    = (float*)(sm + SM_BETA);
    float* psum  = (float*)(sm + SM_PSUM);
    float* psq   = (float*)(sm + SM_PSQ);

    biasS[t] = bias[t];
    if (LN_EPI) {
        gS[t] = gln[t];
        bS[t] = bln[t];
        if (t < 64) { psum[t] = 0.f; psq[t] = 0.f; }
    }

    float c[2][8][4];
#pragma unroll
    for (int i = 0; i < 2; i++)
#pragma unroll
        for (int j = 0; j < 8; j++)
#pragma unroll
            for (int e = 0; e < 4; e++) c[i][j][e] = 0.f;

    const int row_a = t >> 2;
    const int kq_a  = t & 3;
    const int grow_a = bm + row_a;
    const bool aval = (grow_a < M);

    auto lda = [&](int ck, float4& v0, float4& v1) {
        if (aval) {
            size_t off = (size_t)grow_a * H + ck * 32 + kq_a * 8;
            const float4* p = (const float4*)(A0 + off);
            v0 = p[0]; v1 = p[1];
            if (ADDA) {
                const float4* q = (const float4*)(A1 + off);
                float4 u0 = q[0], u1 = q[1];
                v0.x += u0.x; v0.y += u0.y; v0.z += u0.z; v0.w += u0.w;
                v1.x += u1.x; v1.y += u1.y; v1.z += u1.z; v1.w += u1.w;
            }
        } else {
            v0 = make_float4(0.f, 0.f, 0.f, 0.f);
            v1 = v0;
        }
    };
    auto sts_a = [&](int st, float4 v0, float4 v1) {
        float x[8] = {v0.x, v0.y, v0.z, v0.w, v1.x, v1.y, v1.z, v1.w};
        uint32_t hv[4], lv[4];
#pragma unroll
        for (int j = 0; j < 4; j++) {
            __nv_bfloat16 h0 = __float2bfloat16(x[2*j]);
            __nv_bfloat16 h1 = __float2bfloat16(x[2*j+1]);
            float l0 = x[2*j]   - __bfloat162float(h0);
            float l1 = x[2*j+1] - __bfloat162float(h1);
            hv[j] = pack2(__bfloat162float(h0), __bfloat162float(h1));
            lv[j] = pack2(l0, l1);
        }
        uint32_t o = (uint32_t)(row_a * 80 + kq_a * 16);
        *(uint4*)(sm + SM_AH(st) + o) = make_uint4(hv[0], hv[1], hv[2], hv[3]);
        *(uint4*)(sm + SM_AL(st) + o) = make_uint4(lv[0], lv[1], lv[2], lv[3]);
    };
    auto cpb = [&](int ck, int st) {
        const __nv_bfloat16* sh = WtHi + (size_t)t * H + ck * 32;
        const __nv_bfloat16* sl = WtLo + (size_t)t * H + ck * 32;
        uint32_t dh = sb + SM_BH(st) + t * 80;
        uint32_t dl = sb + SM_BL(st) + t * 80;
#pragma unroll
        for (int q = 0; q < 4; q++) {
            cp16(dh + q * 16, sh + q * 8);
            cp16(dl + q * 16, sl + q * 8);
        }
    };

    const uint32_t a_off = (uint32_t)((lane & 15) * 80 + (lane >> 4) * 16);
    const uint32_t b_row = (uint32_t)(wn * 64 + (lane & 7) + ((lane >> 4) * 8));
    const uint32_t b_koff = (uint32_t)(((lane >> 3) & 1) * 16);

    float4 p0, p1, n0, n1;
    lda(0, p0, p1);
    cpb(0, 0);
    CP_COMMIT();

#pragma unroll 1
    for (int ck = 0; ck < 8; ck++) {
        const int st = ck & 1;
        sts_a(st, p0, p1);
        if (ck < 7) {
            lda(ck + 1, n0, n1);
            cpb(ck + 1, st ^ 1);
            CP_COMMIT();
            CP_WAIT1();
        } else {
            CP_WAIT0();
        }
        __syncthreads();

        const uint32_t ah_base = sb + SM_AH(st) + (uint32_t)(wm * 32 * 80) + a_off;
        const uint32_t bh_base = sb + SM_BH(st) + b_row * 80 + b_koff;
#pragma unroll
        for (int ks = 0; ks < 2; ks++) {
            uint32_t ah0[4], ah1[4], al0[4], al1[4];
            uint32_t ab = ah_base + ks * 32;
            ldsm_x4(ah0, ab);
            ldsm_x4(ah1, ab + 16 * 80);
            ldsm_x4(al0, ab + 10240);
            ldsm_x4(al1, ab + 10240 + 16 * 80);
            uint32_t bh[4][4], bl[4][4];
#pragma unroll
            for (int nf4 = 0; nf4 < 4; nf4++) {
                uint32_t bb = bh_base + (uint32_t)(nf4 * 16 * 80) + ks * 32;
                ldsm_x4(bh[nf4], bb);
                ldsm_x4(bl[nf4], bb + 40960);
            }
            // pass 1: Ah * Bh  (16 independent MMAs)
#pragma unroll
            for (int nf4 = 0; nf4 < 4; nf4++) {
                const int nf = nf4 * 2;
                mma_bf16(c[0][nf],     ah0, bh[nf4][0], bh[nf4][1]);
                mma_bf16(c[0][nf + 1], ah0, bh[nf4][2], bh[nf4][3]);
                mma_bf16(c[1][nf],     ah1, bh[nf4][0], bh[nf4][1]);
                mma_bf16(c[1][nf + 1], ah1, bh[nf4][2], bh[nf4][3]);
            }
            // pass 2: Ah * Bl
#pragma unroll
            for (int nf4 = 0; nf4 < 4; nf4++) {
                const int nf = nf4 * 2;
                mma_bf16(c[0][nf],     ah0, bl[nf4][0], bl[nf4][1]);
                mma_bf16(c[0][nf + 1], ah0, bl[nf4][2], bl[nf4][3]);
                mma_bf16(c[1][nf],     ah1, bl[nf4][0], bl[nf4][1]);
                mma_bf16(c[1][nf + 1], ah1, bl[nf4][2], bl[nf4][3]);
            }
            // pass 3: Al * Bh
#pragma unroll
            for (int nf4 = 0; nf4 < 4; nf4++) {
                const int nf = nf4 * 2;
                mma_bf16(c[0][nf],     al0, bh[nf4][0], bh[nf4][1]);
                mma_bf16(c[0][nf + 1], al0, bh[nf4][2], bh[nf4][3]);
                mma_bf16(c[1][nf],     al1, bh[nf4][0], bh[nf4][1]);
                mma_bf16(c[1][nf + 1], al1, bh[nf4][2], bh[nf4][3]);
            }
        }
        __syncthreads();
        p0 = n0; p1 = n1;
    }

    // ---- epilogue ----
    const int qrow = lane >> 2;
    const int qcol = lane & 3;

    if (!LN_EPI) {
#pragma unroll
        for (int mf = 0; mf < 2; mf++)
#pragma unroll
            for (int rh = 0; rh < 2; rh++) {
                int r = wm * 32 + mf * 16 + rh * 8 + qrow;
                int grow = bm + r;
                if (grow >= M) continue;
                float* crow = C + (size_t)grow * H;
#pragma unroll
                for (int nf = 0; nf < 8; nf++) {
                    int col = wn * 64 + nf * 8 + qcol * 2;
                    float2 v;
                    v.x = fmaxf(c[mf][nf][rh * 2]     + biasS[col],     0.f);
                    v.y = fmaxf(c[mf][nf][rh * 2 + 1] + biasS[col + 1], 0.f);
                    *(float2*)(crow + col) = v;
                }
            }
    } else {
#pragma unroll
        for (int mf = 0; mf < 2; mf++)
#pragma unroll
            for (int rh = 0; rh < 2; rh++) {
                int r = wm * 32 + mf * 16 + rh * 8 + qrow;
                int grow = bm + r;
                float su = 0.f, sq = 0.f;
                if (grow < M) {
                    const float* rrow = res + (size_t)grow * H;
#pragma unroll
                    for (int nf = 0; nf < 8; nf++) {
                        int col = wn * 64 + nf * 8 + qcol * 2;
                        float2 rv = *(const float2*)(rrow + col);
                        float z0 = c[mf][nf][rh * 2]     + biasS[col]     + rv.x;
                        float z1 = c[mf][nf][rh * 2 + 1] + biasS[col + 1] + rv.y;
                        c[mf][nf][rh * 2]     = z0;
                        c[mf][nf][rh * 2 + 1] = z1;
                        su += z0 + z1;
                        sq += z0 * z0 + z1 * z1;
                    }
                }
                su += __shfl_xor_sync(0xFFFFFFFFu, su, 1);
                su += __shfl_xor_sync(0xFFFFFFFFu, su, 2);
                sq += __shfl_xor_sync(0xFFFFFFFFu, sq, 1);
                sq += __shfl_xor_sync(0xFFFFFFFFu, sq, 2);
                if (qcol == 0 && grow < M) {
                    atomicAdd(&psum[r], su);
                    atomicAdd(&psq[r], sq);
                }
            }
        __syncthreads();
#pragma unroll
        for (int mf = 0; mf < 2; mf++)
#pragma unroll
            for (int rh = 0; rh < 2; rh++) {
                int r = wm * 32 + mf * 16 + rh * 8 + qrow;
                int grow = bm + r;
                if (grow >= M) continue;
                float mu = psum[r] * (1.f / 256.f);
                float var = psq[r] * (1.f / 256.f) - mu * mu;
                float rs = rsqrtf(var + LN_EPS);
                float* crow = C + (size_t)grow * H;
#pragma unroll
                for (int nf = 0; nf < 8; nf++) {
                    int col = wn * 64 + nf * 8 + qcol * 2;
                    float2 o;
                    o.x = (c[mf][nf][rh * 2]     - mu) * rs * gS[col]     + bS[col];
                    o.y = (c[mf][nf][rh * 2 + 1] - mu) * rs * gS[col + 1] + bS[col + 1];
                    *(float2*)(crow + col) = o;
                }
            }
    }
}

// ---------------------------------------------------------------------------
// launch
// ---------------------------------------------------------------------------
extern "C" void kernel_launch(void* const* d_in, const int* in_sizes, int n_in,
                              void* d_out, int out_size) {
    const float* x_var    = (const float*)d_in[0];
    const float* x_constr = (const float*)d_in[1];
    const int*   ei_v2c   = (const int*)  d_in[2];
    const int*   ei_c2v   = (const int*)  d_in[3];
    const float* ea       = (const float*)d_in[4];
    const float* We1 = (const float*)d_in[5];
    const float* be1 = (const float*)d_in[6];
    const float* W1a = (const float*)d_in[7];
    const float* b1a = (const float*)d_in[8];
    const float* W1b = (const float*)d_in[9];
    const float* b1b = (const float*)d_in[10];
    const float* We2 = (const float*)d_in[11];
    const float* be2 = (const float*)d_in[12];
    const float* W2a = (const float*)d_in[13];
    const float* b2a = (const float*)d_in[14];
    const float* W2b = (const float*)d_in[15];
    const float* b2b = (const float*)d_in[16];
    const float* g_constr    = (const float*)d_in[17];
    const float* beta_constr = (const float*)d_in[18];
    const float* g_var       = (const float*)d_in[19];
    const float* beta_var    = (const float*)d_in[20];

    const int NVr = in_sizes[0] / H;
    const int NCr = in_sizes[1] / H;
    const int Ecnt = in_sizes[4];

    float *agg, *t;
    cudaGetSymbolAddress((void**)&agg, g_agg);
    cudaGetSymbolAddress((void**)&t,   g_t);
    __nv_bfloat16* wt;
    cudaGetSymbolAddress((void**)&wt, g_wt);
    __nv_bfloat16* wt1a_h = wt;             __nv_bfloat16* wt1a_l = wt + H*H;
    __nv_bfloat16* wt1b_h = wt + 2*H*H;     __nv_bfloat16* wt1b_l = wt + 3*H*H;
    __nv_bfloat16* wt2a_h = wt + 4*H*H;     __nv_bfloat16* wt2a_l = wt + 5*H*H;
    __nv_bfloat16* wt2b_h = wt + 6*H*H;     __nv_bfloat16* wt2b_l = wt + 7*H*H;

    cudaFuncSetAttribute(tc_gemm<false, true>,
                         cudaFuncAttributeMaxDynamicSharedMemorySize, SMEM_T);
    cudaFuncSetAttribute(tc_gemm<true, false>,
                         cudaFuncAttributeMaxDynamicSharedMemorySize, SMEM_T);

    float* out_var    = (float*)d_out;
    float* out_constr = (float*)d_out + (size_t)NVr * H;

    const int edge_blocks = (Ecnt + 3) / 4;

    // weight prep (coalesced transpose, 64 blocks each)
    wprep_kernel<<<64, 256>>>(W1a, wt1a_h, wt1a_l);
    wprep_kernel<<<64, 256>>>(W1b, wt1b_h, wt1b_l);
    wprep_kernel<<<64, 256>>>(W2a, wt2a_h, wt2a_l);
    wprep_kernel<<<64, 256>>>(W2b, wt2b_h, wt2b_l);

    // ---- stage 1: var -> constr ----
    {
        int n4 = NCr * H / 4;
        zero_kernel<<<(n4 + 255) / 256, 256>>>((float4*)agg, n4);
        edge_scatter_kernel<<<edge_blocks, 256>>>(x_var, ei_v2c, ei_v2c + Ecnt,
                                                  ea, We1, be1, agg, Ecnt);
        int gx = (NCr + 63) / 64;
        tc_gemm<false, true><<<gx, 256, SMEM_T>>>(
            x_constr, agg, wt1a_h, wt1a_l, b1a, nullptr, nullptr, nullptr, t, NCr);
        tc_gemm<true, false><<<gx, 256, SMEM_T>>>(
            t, nullptr, wt1b_h, wt1b_l, b1b, x_constr, g_constr, beta_constr,
            out_constr, NCr);
    }

    // ---- stage 2: constr -> var (reads LN'd x_constr from d_out) ----
    {
        int n4 = NVr * H / 4;
        zero_kernel<<<(n4 + 255) / 256, 256>>>((float4*)agg, n4);
        edge_scatter_kernel<<<edge_blocks, 256>>>(out_constr, ei_c2v, ei_c2v + Ecnt,
                                                  ea, We2, be2, agg, Ecnt);
        int gx = (NVr + 63) / 64;
        tc_gemm<false, true><<<gx, 256, SMEM_T>>>(
            x_var, agg, wt2a_h, wt2a_l, b2a, nullptr, nullptr, nullptr, t, NVr);
        tc_gemm<true, false><<<gx, 256, SMEM_T>>>(
            t, nullptr, wt2b_h, wt2b_l, b2b, x_var, g_var, beta_var,
            out_var, NVr);
    }
}

// round 5
// speedup vs baseline: 1.5809x; 1.0482x over previous
#include <cuda_runtime.h>
#include <cuda_bf16.h>
#include <cstdint>

#define H 256
#define MAXROWS 50000
#define LN_EPS 1e-5f

// ---------------------------------------------------------------------------
// Scratch (__device__ globals: allocation-free rule)
// ---------------------------------------------------------------------------
__device__ float g_agg[MAXROWS * H];
// Transposed weights as bf16 hi/lo: [which 0..3][hi/lo][n*H + k]
__device__ __nv_bfloat16 g_wt[4][2][H * H];

// ---------------------------------------------------------------------------
// PTX helpers (base compute_103: mma.sync / ldmatrix / cp.async / red.v4)
// ---------------------------------------------------------------------------
__device__ __forceinline__ uint32_t smem_u32(const void* p) {
    uint32_t a;
    asm("{ .reg .u64 t; cvta.to.shared.u64 t, %1; cvt.u32.u64 %0, t; }"
        : "=r"(a) : "l"(p));
    return a;
}
__device__ __forceinline__ void ldsm_x4(uint32_t r[4], uint32_t addr) {
    asm volatile("ldmatrix.sync.aligned.m8n8.x4.shared.b16 {%0,%1,%2,%3}, [%4];"
                 : "=r"(r[0]), "=r"(r[1]), "=r"(r[2]), "=r"(r[3]) : "r"(addr));
}
__device__ __forceinline__ void mma_bf16(float c[4],
                                         const uint32_t a[4],
                                         uint32_t b0, uint32_t b1) {
    asm volatile(
        "mma.sync.aligned.m16n8k16.row.col.f32.bf16.bf16.f32 "
        "{%0,%1,%2,%3}, {%4,%5,%6,%7}, {%8,%9}, {%0,%1,%2,%3};"
        : "+f"(c[0]), "+f"(c[1]), "+f"(c[2]), "+f"(c[3])
        : "r"(a[0]), "r"(a[1]), "r"(a[2]), "r"(a[3]), "r"(b0), "r"(b1));
}
__device__ __forceinline__ void cp16(uint32_t dst, const void* src) {
    asm volatile("cp.async.ca.shared.global [%0], [%1], 16;"
                 :: "r"(dst), "l"(src) : "memory");
}
#define CP_COMMIT() asm volatile("cp.async.commit_group;" ::: "memory")
#define CP_WAIT1()  asm volatile("cp.async.wait_group 1;" ::: "memory")
#define CP_WAIT0()  asm volatile("cp.async.wait_group 0;" ::: "memory")

__device__ __forceinline__ void red_v4(float* addr, float a, float b,
                                       float c, float d) {
    asm volatile("red.global.add.v4.f32 [%0], {%1,%2,%3,%4};"
                 :: "l"(addr), "f"(a), "f"(b), "f"(c), "f"(d) : "memory");
}

__device__ __forceinline__ uint32_t pack2(float a, float b) {
    __nv_bfloat162 h = __floats2bfloat162_rn(a, b);
    return *(uint32_t*)&h;
}

// ---------------------------------------------------------------------------
// SMEM layout (bytes)
//   A chunk tiles: [64][40] bf16, stride 80B. W chunk tiles: [256][40] bf16.
//   h (intermediate) : 8 chunks x [64][40] bf16 hi + lo.
// ---------------------------------------------------------------------------
#define SM_AH(st)  ((st) * 5120)
#define SM_AL(st)  (10240 + (st) * 5120)
#define SM_WH(st)  (20480 + (st) * 20480)
#define SM_WL(st)  (61440 + (st) * 20480)
#define SM_HH      102400
#define SM_HL      143360
#define SM_B1      184320
#define SM_B2      185344
#define SM_G       186368
#define SM_BETA    187392
#define SM_PSUM    188416
#define SM_PSQ     188672
#define SMEM_T     189440

// ---------------------------------------------------------------------------
// zero-fill
// ---------------------------------------------------------------------------
__global__ void zero_kernel(float4* __restrict__ p, int n4) {
    int i = blockIdx.x * blockDim.x + threadIdx.x;
    if (i < n4) p[i] = make_float4(0.f, 0.f, 0.f, 0.f);
}

// ---------------------------------------------------------------------------
// Weight prep (all 4 weights in one launch, coalesced smem transpose)
// ---------------------------------------------------------------------------
__global__ void wprep4_kernel(const float* __restrict__ W0,
                              const float* __restrict__ W1,
                              const float* __restrict__ W2,
                              const float* __restrict__ W3,
                              __nv_bfloat16* __restrict__ base) {
    __shared__ float tile[32][33];
    const int which = blockIdx.x >> 6;
    const float* W = (which == 0) ? W0 : (which == 1) ? W1
                   : (which == 2) ? W2 : W3;
    __nv_bfloat16* hi = base + (size_t)which * 2 * H * H;
    __nv_bfloat16* lo = hi + H * H;
    const int b  = blockIdx.x & 63;
    const int tx = threadIdx.x & 31;
    const int ty = threadIdx.x >> 5;
    const int bx = b & 7;
    const int by = b >> 3;
#pragma unroll
    for (int i = 0; i < 4; i++)
        tile[ty + i * 8][tx] = W[(by * 32 + ty + i * 8) * H + bx * 32 + tx];
    __syncthreads();
#pragma unroll
    for (int i = 0; i < 4; i++) {
        float v = tile[tx][ty + i * 8];
        __nv_bfloat16 h = __float2bfloat16(v);
        int n = bx * 32 + ty + i * 8;
        int k = by * 32 + tx;
        hi[n * H + k] = h;
        lo[n * H + k] = __float2bfloat16(v - __bfloat162float(h));
    }
}

// ---------------------------------------------------------------------------
// Edge scatter: agg[dst] += relu(x_src[src] + ea*We + be)   (vector RED)
// ---------------------------------------------------------------------------
__global__ void edge_scatter_kernel(const float* __restrict__ xsrc,
                                    const int*  __restrict__ src,
                                    const int*  __restrict__ dst,
                                    const float* __restrict__ ea,
                                    const float* __restrict__ We,
                                    const float* __restrict__ be,
                                    float* __restrict__ agg,
                                    int Ecount) {
    int eid = blockIdx.x * 4 + (threadIdx.x >> 6);
    if (eid >= Ecount) return;
    int col = (threadIdx.x & 63) * 4;

    int s = __ldg(src + eid);
    int d = __ldg(dst + eid);
    float a = __ldg(ea + eid);

    float4 x = *(const float4*)(xsrc + (size_t)s * H + col);
    float4 w = __ldg((const float4*)(We + col));
    float4 b = __ldg((const float4*)(be + col));

    float m0 = fmaxf(x.x + fmaf(a, w.x, b.x), 0.f);
    float m1 = fmaxf(x.y + fmaf(a, w.y, b.y), 0.f);
    float m2 = fmaxf(x.z + fmaf(a, w.z, b.z), 0.f);
    float m3 = fmaxf(x.w + fmaf(a, w.w, b.w), 0.f);

    red_v4(agg + (size_t)d * H + col, m0, m1, m2, m3);
}

// ---------------------------------------------------------------------------
// Fused GINE MLP: out = LN( relu((x+agg)@Wa + ba) @ Wb + bb + x ) * g + beta
// Phase A: acc1 = (x+agg)@Wa, epilogue-1 -> h in smem (bf16 hi/lo, A-layout)
// Phase B: acc2 = h@Wb (from smem), epilogue-2 = bias+residual+LayerNorm.
// Tile: 64M x 256N, BK=32, 8 warps (2m x 4n), 3 bf16 passes pass-major.
// ---------------------------------------------------------------------------
__global__ __launch_bounds__(256) void fused_gine(
    const float* __restrict__ X, const float* __restrict__ AGG,
    const __nv_bfloat16* __restrict__ WaHi, const __nv_bfloat16* __restrict__ WaLo,
    const __nv_bfloat16* __restrict__ WbHi, const __nv_bfloat16* __restrict__ WbLo,
    const float* __restrict__ ba, const float* __restrict__ bb,
    const float* __restrict__ gln, const float* __restrict__ bln,
    float* __restrict__ C, int M)
{
    extern __shared__ char sm[];
    const uint32_t sb = smem_u32(sm);

    const int t = threadIdx.x;
    const int lane = t & 31;
    const int wid = t >> 5;
    const int wm = wid & 1;       // 2 m-warps
    const int wn = wid >> 1;      // 4 n-warps
    const int bm = blockIdx.x * 64;

    float* b1S  = (float*)(sm + SM_B1);
    float* b2S  = (float*)(sm + SM_B2);
    float* gS   = (float*)(sm + SM_G);
    float* bS   = (float*)(sm + SM_BETA);
    float* psum = (float*)(sm + SM_PSUM);
    float* psq  = (float*)(sm + SM_PSQ);

    b1S[t] = ba[t];
    b2S[t] = bb[t];
    gS[t]  = gln[t];
    bS[t]  = bln[t];
    if (t < 64) { psum[t] = 0.f; psq[t] = 0.f; }

    float c[2][8][4];
#pragma unroll
    for (int i = 0; i < 2; i++)
#pragma unroll
        for (int j = 0; j < 8; j++)
#pragma unroll
            for (int e = 0; e < 4; e++) c[i][j][e] = 0.f;

    const int row_a = t >> 2;
    const int kq_a  = t & 3;
    const int grow_a = bm + row_a;
    const bool aval = (grow_a < M);

    auto lda = [&](int ck, float4& v0, float4& v1) {
        if (aval) {
            size_t off = (size_t)grow_a * H + ck * 32 + kq_a * 8;
            const float4* p = (const float4*)(X + off);
            const float4* q = (const float4*)(AGG + off);
            float4 a0 = p[0], a1 = p[1];
            float4 u0 = q[0], u1 = q[1];
            v0.x = a0.x + u0.x; v0.y = a0.y + u0.y;
            v0.z = a0.z + u0.z; v0.w = a0.w + u0.w;
            v1.x = a1.x + u1.x; v1.y = a1.y + u1.y;
            v1.z = a1.z + u1.z; v1.w = a1.w + u1.w;
        } else {
            v0 = make_float4(0.f, 0.f, 0.f, 0.f);
            v1 = v0;
        }
    };
    auto sts_a = [&](int st, float4 v0, float4 v1) {
        float x[8] = {v0.x, v0.y, v0.z, v0.w, v1.x, v1.y, v1.z, v1.w};
        uint32_t hv[4], lv[4];
#pragma unroll
        for (int j = 0; j < 4; j++) {
            __nv_bfloat16 h0 = __float2bfloat16(x[2*j]);
            __nv_bfloat16 h1 = __float2bfloat16(x[2*j+1]);
            float l0 = x[2*j]   - __bfloat162float(h0);
            float l1 = x[2*j+1] - __bfloat162float(h1);
            hv[j] = pack2(__bfloat162float(h0), __bfloat162float(h1));
            lv[j] = pack2(l0, l1);
        }
        uint32_t o = (uint32_t)(row_a * 80 + kq_a * 16);
        *(uint4*)(sm + SM_AH(st) + o) = make_uint4(hv[0], hv[1], hv[2], hv[3]);
        *(uint4*)(sm + SM_AL(st) + o) = make_uint4(lv[0], lv[1], lv[2], lv[3]);
    };
    auto cpw = [&](const __nv_bfloat16* WHi, const __nv_bfloat16* WLo,
                   int ck, int st) {
        const __nv_bfloat16* sh = WHi + (size_t)t * H + ck * 32;
        const __nv_bfloat16* sl = WLo + (size_t)t * H + ck * 32;
        uint32_t dh = sb + SM_WH(st) + t * 80;
        uint32_t dl = sb + SM_WL(st) + t * 80;
#pragma unroll
        for (int q = 0; q < 4; q++) {
            cp16(dh + q * 16, sh + q * 8);
            cp16(dl + q * 16, sl + q * 8);
        }
    };

    const uint32_t a_off  = (uint32_t)((lane & 15) * 80 + (lane >> 4) * 16);
    const uint32_t b_row  = (uint32_t)(wn * 64 + (lane & 7) + ((lane >> 4) * 8));
    const uint32_t b_koff = (uint32_t)(((lane >> 3) & 1) * 16);

    // triple-pass MMA over one 32-K chunk.
    // aHi: A hi base addr (chunk), aLD: lo delta; wHi: W hi base (lo at +40960)
    auto compute = [&](uint32_t aHi, uint32_t aLD, uint32_t wHi) {
        const uint32_t ah_base = aHi + (uint32_t)(wm * 2560) + a_off;
        const uint32_t wh_base = wHi + b_row * 80 + b_koff;
#pragma unroll
        for (int ks = 0; ks < 2; ks++) {
            uint32_t ah0[4], ah1[4], al0[4], al1[4];
            uint32_t ab = ah_base + ks * 32;
            ldsm_x4(ah0, ab);
            ldsm_x4(ah1, ab + 16 * 80);
            ldsm_x4(al0, ab + aLD);
            ldsm_x4(al1, ab + aLD + 16 * 80);
            uint32_t bh[4][4], bl[4][4];
#pragma unroll
            for (int nf4 = 0; nf4 < 4; nf4++) {
                uint32_t bb_ = wh_base + (uint32_t)(nf4 * 16 * 80) + ks * 32;
                ldsm_x4(bh[nf4], bb_);
                ldsm_x4(bl[nf4], bb_ + 40960);
            }
#pragma unroll
            for (int nf4 = 0; nf4 < 4; nf4++) {
                const int nf = nf4 * 2;
                mma_bf16(c[0][nf],     ah0, bh[nf4][0], bh[nf4][1]);
                mma_bf16(c[0][nf + 1], ah0, bh[nf4][2], bh[nf4][3]);
                mma_bf16(c[1][nf],     ah1, bh[nf4][0], bh[nf4][1]);
                mma_bf16(c[1][nf + 1], ah1, bh[nf4][2], bh[nf4][3]);
            }
#pragma unroll
            for (int nf4 = 0; nf4 < 4; nf4++) {
                const int nf = nf4 * 2;
                mma_bf16(c[0][nf],     ah0, bl[nf4][0], bl[nf4][1]);
                mma_bf16(c[0][nf + 1], ah0, bl[nf4][2], bl[nf4][3]);
                mma_bf16(c[1][nf],     ah1, bl[nf4][0], bl[nf4][1]);
                mma_bf16(c[1][nf + 1], ah1, bl[nf4][2], bl[nf4][3]);
            }
#pragma unroll
            for (int nf4 = 0; nf4 < 4; nf4++) {
                const int nf = nf4 * 2;
                mma_bf16(c[0][nf],     al0, bh[nf4][0], bh[nf4][1]);
                mma_bf16(c[0][nf + 1], al0, bh[nf4][2], bh[nf4][3]);
                mma_bf16(c[1][nf],     al1, bh[nf4][0], bh[nf4][1]);
                mma_bf16(c[1][nf + 1], al1, bh[nf4][2], bh[nf4][3]);
            }
        }
    };

    const int qrow = lane >> 2;
    const int qcol = lane & 3;

    // =================== Phase A: acc1 = (X+AGG) @ Wa ===================
    float4 p0, p1, n0, n1;
    lda(0, p0, p1);
    cpw(WaHi, WaLo, 0, 0);
    CP_COMMIT();

#pragma unroll 1
    for (int ck = 0; ck < 8; ck++) {
        const int st = ck & 1;
        sts_a(st, p0, p1);
        if (ck < 7) {
            lda(ck + 1, n0, n1);
            cpw(WaHi, WaLo, ck + 1, st ^ 1);
            CP_COMMIT();
            CP_WAIT1();
        } else {
            CP_WAIT0();
        }
        __syncthreads();
        compute(sb + SM_AH(st), 10240, sb + SM_WH(st));
        __syncthreads();
        p0 = n0; p1 = n1;
    }

    // ---- epilogue 1: h = relu(acc1 + ba) -> smem (bf16 hi/lo, A layout) ----
#pragma unroll
    for (int mf = 0; mf < 2; mf++)
#pragma unroll
        for (int rh = 0; rh < 2; rh++) {
            int r = wm * 32 + mf * 16 + rh * 8 + qrow;
#pragma unroll
            for (int nf = 0; nf < 8; nf++) {
                int kcol = wn * 64 + nf * 8 + qcol * 2;
                float z0 = fmaxf(c[mf][nf][rh * 2]     + b1S[kcol],     0.f);
                float z1 = fmaxf(c[mf][nf][rh * 2 + 1] + b1S[kcol + 1], 0.f);
                __nv_bfloat16 h0 = __float2bfloat16(z0);
                __nv_bfloat16 h1 = __float2bfloat16(z1);
                float l0 = z0 - __bfloat162float(h0);
                float l1 = z1 - __bfloat162float(h1);
                uint32_t off = (uint32_t)((kcol >> 5) * 5120 + r * 80
                                          + (kcol & 31) * 2);
                *(uint32_t*)(sm + SM_HH + off) =
                    pack2(__bfloat162float(h0), __bfloat162float(h1));
                *(uint32_t*)(sm + SM_HL + off) = pack2(l0, l1);
            }
        }

    // zero accumulators for phase B
#pragma unroll
    for (int i = 0; i < 2; i++)
#pragma unroll
        for (int j = 0; j < 8; j++)
#pragma unroll
            for (int e = 0; e < 4; e++) c[i][j][e] = 0.f;

    // =================== Phase B: acc2 = h @ Wb =========================
    cpw(WbHi, WbLo, 0, 0);
    CP_COMMIT();

#pragma unroll 1
    for (int ck = 0; ck < 8; ck++) {
        const int st = ck & 1;
        if (ck < 7) {
            cpw(WbHi, WbLo, ck + 1, st ^ 1);
            CP_COMMIT();
            CP_WAIT1();
        } else {
            CP_WAIT0();
        }
        __syncthreads();
        compute(sb + SM_HH + ck * 5120, 40960, sb + SM_WH(st));
        __syncthreads();
    }

    // ---- epilogue 2: LN(acc2 + bb + X) * g + beta ----
#pragma unroll
    for (int mf = 0; mf < 2; mf++)
#pragma unroll
        for (int rh = 0; rh < 2; rh++) {
            int r = wm * 32 + mf * 16 + rh * 8 + qrow;
            int grow = bm + r;
            float su = 0.f, sq = 0.f;
            if (grow < M) {
                const float* rrow = X + (size_t)grow * H;
#pragma unroll
                for (int nf = 0; nf < 8; nf++) {
                    int col = wn * 64 + nf * 8 + qcol * 2;
                    float2 rv = *(const float2*)(rrow + col);
                    float z0 = c[mf][nf][rh * 2]     + b2S[col]     + rv.x;
                    float z1 = c[mf][nf][rh * 2 + 1] + b2S[col + 1] + rv.y;
                    c[mf][nf][rh * 2]     = z0;
                    c[mf][nf][rh * 2 + 1] = z1;
                    su += z0 + z1;
                    sq += z0 * z0 + z1 * z1;
                }
            }
            su += __shfl_xor_sync(0xFFFFFFFFu, su, 1);
            su += __shfl_xor_sync(0xFFFFFFFFu, su, 2);
            sq += __shfl_xor_sync(0xFFFFFFFFu, sq, 1);
            sq += __shfl_xor_sync(0xFFFFFFFFu, sq, 2);
            if (qcol == 0 && grow < M) {
                atomicAdd(&psum[r], su);
                atomicAdd(&psq[r], sq);
            }
        }
    __syncthreads();
#pragma unroll
    for (int mf = 0; mf < 2; mf++)
#pragma unroll
        for (int rh = 0; rh < 2; rh++) {
            int r = wm * 32 + mf * 16 + rh * 8 + qrow;
            int grow = bm + r;
            if (grow >= M) continue;
            float mu = psum[r] * (1.f / 256.f);
            float var = psq[r] * (1.f / 256.f) - mu * mu;
            float rs = rsqrtf(var + LN_EPS);
            float* crow = C + (size_t)grow * H;
#pragma unroll
            for (int nf = 0; nf < 8; nf++) {
                int col = wn * 64 + nf * 8 + qcol * 2;
                float2 o;
                o.x = (c[mf][nf][rh * 2]     - mu) * rs * gS[col]     + bS[col];
                o.y = (c[mf][nf][rh * 2 + 1] - mu) * rs * gS[col + 1] + bS[col + 1];
                *(float2*)(crow + col) = o;
            }
        }
}

// ---------------------------------------------------------------------------
// launch
// ---------------------------------------------------------------------------
extern "C" void kernel_launch(void* const* d_in, const int* in_sizes, int n_in,
                              void* d_out, int out_size) {
    const float* x_var    = (const float*)d_in[0];
    const float* x_constr = (const float*)d_in[1];
    const int*   ei_v2c   = (const int*)  d_in[2];
    const int*   ei_c2v   = (const int*)  d_in[3];
    const float* ea       = (const float*)d_in[4];
    const float* We1 = (const float*)d_in[5];
    const float* be1 = (const float*)d_in[6];
    const float* W1a = (const float*)d_in[7];
    const float* b1a = (const float*)d_in[8];
    const float* W1b = (const float*)d_in[9];
    const float* b1b = (const float*)d_in[10];
    const float* We2 = (const float*)d_in[11];
    const float* be2 = (const float*)d_in[12];
    const float* W2a = (const float*)d_in[13];
    const float* b2a = (const float*)d_in[14];
    const float* W2b = (const float*)d_in[15];
    const float* b2b = (const float*)d_in[16];
    const float* g_constr    = (const float*)d_in[17];
    const float* beta_constr = (const float*)d_in[18];
    const float* g_var       = (const float*)d_in[19];
    const float* beta_var    = (const float*)d_in[20];

    const int NVr = in_sizes[0] / H;
    const int NCr = in_sizes[1] / H;
    const int Ecnt = in_sizes[4];

    float* agg;
    cudaGetSymbolAddress((void**)&agg, g_agg);
    __nv_bfloat16* wt;
    cudaGetSymbolAddress((void**)&wt, g_wt);
    __nv_bfloat16* wt1a_h = wt;             __nv_bfloat16* wt1a_l = wt + H*H;
    __nv_bfloat16* wt1b_h = wt + 2*H*H;     __nv_bfloat16* wt1b_l = wt + 3*H*H;
    __nv_bfloat16* wt2a_h = wt + 4*H*H;     __nv_bfloat16* wt2a_l = wt + 5*H*H;
    __nv_bfloat16* wt2b_h = wt + 6*H*H;     __nv_bfloat16* wt2b_l = wt + 7*H*H;

    cudaFuncSetAttribute(fused_gine,
                         cudaFuncAttributeMaxDynamicSharedMemorySize, SMEM_T);

    float* out_var    = (float*)d_out;
    float* out_constr = (float*)d_out + (size_t)NVr * H;

    const int edge_blocks = (Ecnt + 3) / 4;

    // weight prep: all 4 weights, one launch (order: W1a, W1b, W2a, W2b)
    wprep4_kernel<<<256, 256>>>(W1a, W1b, W2a, W2b, wt);

    // ---- stage 1: var -> constr ----
    {
        int n4 = NCr * H / 4;
        zero_kernel<<<(n4 + 255) / 256, 256>>>((float4*)agg, n4);
        edge_scatter_kernel<<<edge_blocks, 256>>>(x_var, ei_v2c, ei_v2c + Ecnt,
                                                  ea, We1, be1, agg, Ecnt);
        int gx = (NCr + 63) / 64;
        fused_gine<<<gx, 256, SMEM_T>>>(
            x_constr, agg, wt1a_h, wt1a_l, wt1b_h, wt1b_l,
            b1a, b1b, g_constr, beta_constr, out_constr, NCr);
    }

    // ---- stage 2: constr -> var (reads LN'd x_constr from d_out) ----
    {
        int n4 = NVr * H / 4;
        zero_kernel<<<(n4 + 255) / 256, 256>>>((float4*)agg, n4);
        edge_scatter_kernel<<<edge_blocks, 256>>>(out_constr, ei_c2v, ei_c2v + Ecnt,
                                                  ea, We2, be2, agg, Ecnt);
        int gx = (NVr + 63) / 64;
        fused_gine<<<gx, 256, SMEM_T>>>(
            x_var, agg, wt2a_h, wt2a_l, wt2b_h, wt2b_l,
            b2a, b2b, g_var, beta_var, out_var, NVr);
    }
}